// round 3
// baseline (speedup 1.0000x reference)
#include <cuda_runtime.h>
#include <math.h>

#define BATCH 2048
#define DM 256
#define NF 32768
#define NB 8

#define BM 128
#define BN 128
#define BK 16

// ---------------- device scratch (no allocations allowed) ----------------
__device__ float g_blockacc[(size_t)NB * BATCH * DM];  // 16 MB block partial preds
__device__ float g_wdn[NF];
__device__ float g_cw[NB];
__device__ float g_scale;
__device__ float g_normsum;
__device__ double g_l1;
__device__ double g_mse;
__device__ unsigned long long g_l0;

// ---------------- zero scratch ----------------
__global__ void k_zero() {
    size_t n = (size_t)NB * BATCH * DM;
    for (size_t i = (size_t)blockIdx.x * blockDim.x + threadIdx.x; i < n;
         i += (size_t)gridDim.x * blockDim.x)
        g_blockacc[i] = 0.f;
    if (blockIdx.x == 0 && threadIdx.x == 0) {
        g_normsum = 0.f; g_l1 = 0.0; g_mse = 0.0; g_l0 = 0ull;
    }
}

// ---------------- mean row norm of x ----------------
__global__ void k_xnorm(const float* __restrict__ x) {
    int warp = threadIdx.x >> 5, lane = threadIdx.x & 31;
    int row = blockIdx.x * 8 + warp;
    const float* xr = x + (size_t)row * DM;
    float s = 0.f;
#pragma unroll
    for (int i = 0; i < DM / 32; i++) { float v = xr[lane + 32 * i]; s += v * v; }
#pragma unroll
    for (int o = 16; o > 0; o >>= 1) s += __shfl_down_sync(0xffffffffu, s, o);
    if (lane == 0) atomicAdd(&g_normsum, sqrtf(s));
}

// ---------------- W_dec row norms ----------------
__global__ void k_wdn(const float* __restrict__ W_dec) {
    int warp = threadIdx.x >> 5, lane = threadIdx.x & 31;
    int row = blockIdx.x * 8 + warp;
    const float* wr = W_dec + (size_t)row * DM;
    float s = 0.f;
#pragma unroll
    for (int i = 0; i < DM / 32; i++) { float v = wr[lane + 32 * i]; s += v * v; }
#pragma unroll
    for (int o = 16; o > 0; o >>= 1) s += __shfl_down_sync(0xffffffffu, s, o);
    if (lane == 0) g_wdn[row] = sqrtf(s);
}

// ---------------- scalar prep: scale + cumulative-tail block weights ----------------
__global__ void k_prep(const float* __restrict__ running_avg, const float* __restrict__ bw) {
    float one_minus = (float)(1.0 - 0.99);
    float ra = 0.99f * running_avg[0] + one_minus * (g_normsum / (float)BATCH);
    g_scale = sqrtf((float)DM) / ra;
    float tot = 0.f;
    for (int j = NB - 1; j >= 0; j--) { tot += bw[j]; g_cw[j] = tot / (float)NB; }
}

// ---------------- main fused kernel ----------------
struct SmemMain {
    float As[BK][BM + 4];       // x tile, [k][row]
    float Bs[BK][BN + 4];       // W_enc / W_dec tile, [k][col]
    float actsS[BN][BM + 4];    // acts tile, [feature][row]
    float sbenc[BN];
    float swdn[BN];
    float scwf[BN];
    int   segs[BN];
    int   runs[BN + 1];
    int   nrun;
};

__global__ __launch_bounds__(256) void k_main(
    const float* __restrict__ x, const float* __restrict__ W_enc,
    const float* __restrict__ b_enc, const float* __restrict__ W_dec,
    const int* __restrict__ seg)
{
    extern __shared__ char smraw[];
    SmemMain& sm = *reinterpret_cast<SmemMain*>(smraw);
    const int tid = threadIdx.x;
    const int tx = tid & 15, ty = tid >> 4;
    const int f0 = blockIdx.x * BN;
    const int b0 = blockIdx.y * BM;
    const float scale = g_scale;

    if (tid < BN) {
        int f = f0 + tid;
        int s = seg[f];
        sm.segs[tid]  = s;
        sm.sbenc[tid] = b_enc[f];
        sm.swdn[tid]  = g_wdn[f];
        sm.scwf[tid]  = g_cw[s];
    }
    __syncthreads();
    if (tid == 0) {  // seg-run detection (seg is monotone; usually 1 run/tile)
        int n = 0; sm.runs[0] = 0;
        for (int k = 1; k < BN; k++)
            if (sm.segs[k] != sm.segs[k - 1]) sm.runs[++n] = k;
        sm.runs[n + 1] = BN; sm.nrun = n + 1;
    }

    // ---- GEMM1: raw = x_tile @ W_enc_tile, K = 256 ----
    float acc[8][8];
#pragma unroll
    for (int i = 0; i < 8; i++)
#pragma unroll
        for (int j = 0; j < 8; j++) acc[i][j] = 0.f;

    for (int k0 = 0; k0 < DM; k0 += BK) {
#pragma unroll
        for (int i = 0; i < 8; i++) {
            int idx = i * 256 + tid;
            int row = idx >> 4, kk = idx & 15;
            sm.As[kk][row] = x[(size_t)(b0 + row) * DM + k0 + kk];
        }
#pragma unroll
        for (int i = 0; i < 8; i++) {
            int idx = i * 256 + tid;
            int kk = idx >> 7, col = idx & 127;
            sm.Bs[kk][col] = W_enc[(size_t)(k0 + kk) * NF + f0 + col];
        }
        __syncthreads();
#pragma unroll
        for (int k = 0; k < BK; k++) {
            float4 a0 = *(const float4*)&sm.As[k][ty * 8];
            float4 a1 = *(const float4*)&sm.As[k][ty * 8 + 4];
            float4 bb0 = *(const float4*)&sm.Bs[k][tx * 8];
            float4 bb1 = *(const float4*)&sm.Bs[k][tx * 8 + 4];
            float a[8] = {a0.x, a0.y, a0.z, a0.w, a1.x, a1.y, a1.z, a1.w};
            float b[8] = {bb0.x, bb0.y, bb0.z, bb0.w, bb1.x, bb1.y, bb1.z, bb1.w};
#pragma unroll
            for (int i = 0; i < 8; i++)
#pragma unroll
                for (int j = 0; j < 8; j++) acc[i][j] = fmaf(a[i], b[j], acc[i][j]);
        }
        __syncthreads();
    }

    // ---- epilogue: relu + L1/L0 scalar terms, stash acts to smem ----
    float l1p = 0.f; int l0p = 0;
#pragma unroll
    for (int j = 0; j < 8; j++) {
        int col = tx * 8 + j;
        float be = sm.sbenc[col], wn = sm.swdn[col], cw = sm.scwf[col];
#pragma unroll
        for (int i = 0; i < 8; i++) {
            float act = fmaf(scale, acc[i][j], be);
            act = fmaxf(act, 0.f);
            if (act > 0.f) {
                l0p++;
                // log(a*wn + 0.1) - log(0.1) == log1p(10*a*wn)
                l1p += cw * __logf(fmaf(10.f * wn, act, 1.f));
            }
            sm.actsS[col][ty * 8 + i] = act;
        }
    }
#pragma unroll
    for (int o = 16; o > 0; o >>= 1) {
        l1p += __shfl_down_sync(0xffffffffu, l1p, o);
        l0p += __shfl_down_sync(0xffffffffu, l0p, o);
    }
    if ((tid & 31) == 0) {
        atomicAdd(&g_l1, (double)l1p);
        atomicAdd(&g_l0, (unsigned long long)l0p);
    }
    __syncthreads();

    // ---- GEMM2 per seg-run: acts @ W_dec -> atomic accumulate into block ----
    const int nrun = sm.nrun;
    for (int r = 0; r < nrun; r++) {
        const int ka = sm.runs[r], kb = sm.runs[r + 1];
        const int blk = sm.segs[ka];
        float* dstbase = g_blockacc + ((size_t)blk * BATCH + b0) * DM;
        for (int dh = 0; dh < 2; dh++) {
            float c[8][8];
#pragma unroll
            for (int i = 0; i < 8; i++)
#pragma unroll
                for (int j = 0; j < 8; j++) c[i][j] = 0.f;

            for (int k0 = ka & ~(BK - 1); k0 < kb; k0 += BK) {
#pragma unroll
                for (int i = 0; i < 8; i++) {
                    int idx = i * 256 + tid;
                    int kk = idx >> 7, col = idx & 127;
                    sm.Bs[kk][col] = W_dec[(size_t)(f0 + k0 + kk) * DM + dh * 128 + col];
                }
                __syncthreads();
#pragma unroll
                for (int k = 0; k < BK; k++) {
                    int kk = k0 + k;
                    if (kk >= ka && kk < kb) {  // uniform predicate (run bounds are CTA-uniform)
                        float4 a0 = *(const float4*)&sm.actsS[kk][ty * 8];
                        float4 a1 = *(const float4*)&sm.actsS[kk][ty * 8 + 4];
                        float4 bb0 = *(const float4*)&sm.Bs[k][tx * 8];
                        float4 bb1 = *(const float4*)&sm.Bs[k][tx * 8 + 4];
                        float a[8] = {a0.x, a0.y, a0.z, a0.w, a1.x, a1.y, a1.z, a1.w};
                        float b[8] = {bb0.x, bb0.y, bb0.z, bb0.w, bb1.x, bb1.y, bb1.z, bb1.w};
#pragma unroll
                        for (int i = 0; i < 8; i++)
#pragma unroll
                            for (int j = 0; j < 8; j++) c[i][j] = fmaf(a[i], b[j], c[i][j]);
                    }
                }
                __syncthreads();
            }
#pragma unroll
            for (int i = 0; i < 8; i++) {
                float* dst = dstbase + (size_t)(ty * 8 + i) * DM + dh * 128 + tx * 8;
#pragma unroll
                for (int j = 0; j < 8; j++) atomicAdd(&dst[j], c[i][j]);
            }
        }
    }
}

// ---------------- per-row cumulative-block MSE ----------------
__global__ void k_mse(const float* __restrict__ x, const float* __restrict__ b_dec,
                      const float* __restrict__ bw) {
    __shared__ float sbw[NB];
    __shared__ float red[8];
    int b = blockIdx.x, d = threadIdx.x;
    if (d < NB) sbw[d] = bw[d];
    __syncthreads();
    float xn = x[(size_t)b * DM + d] * g_scale;
    float cum = b_dec[d];
    float t = 0.f;
#pragma unroll
    for (int k = 0; k < NB; k++) {
        cum += g_blockacc[((size_t)k * BATCH + b) * DM + d];
        float diff = cum - xn;
        t += sbw[k] * diff * diff;
    }
#pragma unroll
    for (int o = 16; o > 0; o >>= 1) t += __shfl_down_sync(0xffffffffu, t, o);
    if ((d & 31) == 0) red[d >> 5] = t;
    __syncthreads();
    if (d < 8) {
        t = red[d];
#pragma unroll
        for (int o = 4; o > 0; o >>= 1) t += __shfl_down_sync(0xffu, t, o);
        if (d == 0) atomicAdd(&g_mse, (double)t);
    }
}

// ---------------- combine ----------------
__global__ void k_final(const float* __restrict__ l1_scale, float* __restrict__ out) {
    double mse = g_mse / ((double)NB * (double)BATCH);
    double l1  = g_l1 / (double)BATCH;
    float avg_l0 = (float)((double)g_l0 / (double)BATCH);
    float reg = l1_scale[0] * (avg_l0 < 100.0f ? (1.0f - 3e-4f) : (1.0f + 3e-4f));
    out[0] = (float)(mse + (double)reg * (double)l1);
}

// ---------------- launch ----------------
extern "C" void kernel_launch(void* const* d_in, const int* in_sizes, int n_in,
                              void* d_out, int out_size) {
    const float* x     = (const float*)d_in[0];
    const float* W_enc = (const float*)d_in[1];
    const float* b_enc = (const float*)d_in[2];
    const float* W_dec = (const float*)d_in[3];
    const float* b_dec = (const float*)d_in[4];
    const float* bw    = (const float*)d_in[5];
    const float* ravg  = (const float*)d_in[6];
    const float* l1s   = (const float*)d_in[7];
    const int*   seg   = (const int*)d_in[8];
    float* out = (float*)d_out;

    cudaFuncSetAttribute(k_main, cudaFuncAttributeMaxDynamicSharedMemorySize,
                         (int)sizeof(SmemMain));

    k_zero<<<2048, 256>>>();
    k_xnorm<<<BATCH / 8, 256>>>(x);
    k_wdn<<<NF / 8, 256>>>(W_dec);
    k_prep<<<1, 1>>>(ravg, bw);
    dim3 grid(NF / BN, BATCH / BM);
    k_main<<<grid, 256, sizeof(SmemMain)>>>(x, W_enc, b_enc, W_dec, seg);
    k_mse<<<BATCH, 256>>>(x, b_dec, bw);
    k_final<<<1, 1>>>(l1s, out);
}

// round 4
// speedup vs baseline: 2.8485x; 2.8485x over previous
#include <cuda_runtime.h>
#include <math.h>
#include <stdint.h>

#define BATCH 2048
#define DM 256
#define NF 32768
#define NB 8
#define FC 1024            // features per chunk (per CTA)
#define NCH (NF / FC)      // 32 chunks
#define NST (FC / 128)     // 8 subtiles per chunk

// ---------------- device scratch (static; no allocations allowed) ----------------
__device__ float g_blockacc[(size_t)NB * BATCH * DM];   // 16 MB
__device__ float g_wenc32[(size_t)DM * NF];             // tf32(rna) W_enc
__device__ float g_wdec32[(size_t)NF * DM];             // tf32(rna) W_dec
__device__ float g_xn[(size_t)BATCH * DM];              // tf32(rna) x*scale
__device__ float g_wdn[NF];
__device__ float g_cw[NB];
__device__ float g_scale;
__device__ float g_normsum;
__device__ double g_l1;
__device__ double g_mse;
__device__ unsigned long long g_l0;

// ---------------- helpers ----------------
__device__ __forceinline__ uint32_t smem_to_u32(const void* p) {
    uint32_t a;
    asm("{ .reg .u64 t; cvta.to.shared.u64 t, %1; cvt.u32.u64 %0, t; }" : "=r"(a) : "l"(p));
    return a;
}
__device__ __forceinline__ void cpa16(uint32_t s, const void* g) {
    asm volatile("cp.async.ca.shared.global [%0], [%1], 16;" :: "r"(s), "l"(g));
}
#define CP_COMMIT() asm volatile("cp.async.commit_group;")
#define CP_WAIT0()  asm volatile("cp.async.wait_group 0;")
#define CP_WAIT1()  asm volatile("cp.async.wait_group 1;")

__device__ __forceinline__ void mma_tf32(float* d, const uint32_t* a, const uint32_t* b) {
    asm volatile(
        "mma.sync.aligned.m16n8k8.row.col.f32.tf32.tf32.f32 "
        "{%0,%1,%2,%3}, {%4,%5,%6,%7}, {%8,%9}, {%0,%1,%2,%3};"
        : "+f"(d[0]), "+f"(d[1]), "+f"(d[2]), "+f"(d[3])
        : "r"(a[0]), "r"(a[1]), "r"(a[2]), "r"(a[3]), "r"(b[0]), "r"(b[1]));
}
__device__ __forceinline__ uint32_t rna_tf32(float v) {
    uint32_t u;
    asm("cvt.rna.tf32.f32 %0, %1;" : "=r"(u) : "f"(v));
    return u;
}

// ---------------- aux kernels ----------------
__global__ void k_zero() {
    size_t n = (size_t)NB * BATCH * DM;
    for (size_t i = (size_t)blockIdx.x * blockDim.x + threadIdx.x; i < n;
         i += (size_t)gridDim.x * blockDim.x)
        g_blockacc[i] = 0.f;
    if (blockIdx.x == 0 && threadIdx.x == 0) {
        g_normsum = 0.f; g_l1 = 0.0; g_mse = 0.0; g_l0 = 0ull;
    }
}

__global__ void k_xnorm(const float* __restrict__ x) {
    int warp = threadIdx.x >> 5, lane = threadIdx.x & 31;
    int row = blockIdx.x * 8 + warp;
    const float* xr = x + (size_t)row * DM;
    float s = 0.f;
#pragma unroll
    for (int i = 0; i < DM / 32; i++) { float v = xr[lane + 32 * i]; s += v * v; }
#pragma unroll
    for (int o = 16; o > 0; o >>= 1) s += __shfl_down_sync(0xffffffffu, s, o);
    if (lane == 0) atomicAdd(&g_normsum, sqrtf(s));
}

__global__ void k_wdn(const float* __restrict__ W_dec) {
    int warp = threadIdx.x >> 5, lane = threadIdx.x & 31;
    int row = blockIdx.x * 8 + warp;
    const float* wr = W_dec + (size_t)row * DM;
    float s = 0.f;
#pragma unroll
    for (int i = 0; i < DM / 32; i++) { float v = wr[lane + 32 * i]; s += v * v; }
#pragma unroll
    for (int o = 16; o > 0; o >>= 1) s += __shfl_down_sync(0xffffffffu, s, o);
    if (lane == 0) g_wdn[row] = sqrtf(s);
}

__global__ void k_prep(const float* __restrict__ running_avg, const float* __restrict__ bw) {
    float ra = 0.99f * running_avg[0] + 0.01f * (g_normsum / (float)BATCH);
    g_scale = sqrtf((float)DM) / ra;
    float tot = 0.f;
    for (int j = NB - 1; j >= 0; j--) { tot += bw[j]; g_cw[j] = tot / (float)NB; }
}

__global__ void k_cvt_enc(const float* __restrict__ src) {
    size_t i = (size_t)blockIdx.x * blockDim.x + threadIdx.x;
    float4 v = ((const float4*)src)[i];
    float4 o;
    o.x = __uint_as_float(rna_tf32(v.x));
    o.y = __uint_as_float(rna_tf32(v.y));
    o.z = __uint_as_float(rna_tf32(v.z));
    o.w = __uint_as_float(rna_tf32(v.w));
    ((float4*)g_wenc32)[i] = o;
}
__global__ void k_cvt_dec(const float* __restrict__ src) {
    size_t i = (size_t)blockIdx.x * blockDim.x + threadIdx.x;
    float4 v = ((const float4*)src)[i];
    float4 o;
    o.x = __uint_as_float(rna_tf32(v.x));
    o.y = __uint_as_float(rna_tf32(v.y));
    o.z = __uint_as_float(rna_tf32(v.z));
    o.w = __uint_as_float(rna_tf32(v.w));
    ((float4*)g_wdec32)[i] = o;
}
__global__ void k_xn(const float* __restrict__ x) {
    size_t i = (size_t)blockIdx.x * blockDim.x + threadIdx.x;
    float sc = g_scale;
    float4 v = ((const float4*)x)[i];
    float4 o;
    o.x = __uint_as_float(rna_tf32(v.x * sc));
    o.y = __uint_as_float(rna_tf32(v.y * sc));
    o.z = __uint_as_float(rna_tf32(v.z * sc));
    o.w = __uint_as_float(rna_tf32(v.w * sc));
    ((float4*)g_xn)[i] = o;
}

// ---------------- smem layout (floats) ----------------
// acts   [128][132]           : 0      .. 16896
// xn     2 x [128][20]        : 16896  .. 22016
// wenc   2 x [16][136]        : 22016  .. 26368
// wdec   2 x [16][264]        : 26368  .. 34816
// benc   [1024]               : 34816
// wdn    [1024]               : 35840
// cwf    [1024]               : 36864
// segs   [1024] int           : 37888
// runs   [12] int             : 38912
// blk    [8] int              : 38924
// cnt    [1] int              : 38932
// tmp    [8] int              : 38936  .. 38944
#define SMEM_FLOATS 38944
#define SMEM_BYTES (SMEM_FLOATS * 4)

__global__ __launch_bounds__(512, 1) void k_main(
    const float* __restrict__ b_enc, const int* __restrict__ seg)
{
    extern __shared__ float smf[];
    float* acts_s = smf;
    float* xn_s   = smf + 16896;
    float* we_s   = smf + 22016;
    float* wd_s   = smf + 26368;
    float* benc_s = smf + 34816;
    float* wdn_s  = smf + 35840;
    float* cwf_s  = smf + 36864;
    int*   segs_s = (int*)(smf + 37888);
    int*   runs_s = (int*)(smf + 38912);
    int*   blk_s  = (int*)(smf + 38924);
    int*   cnt_s  = (int*)(smf + 38932);
    int*   tmp_s  = (int*)(smf + 38936);

    const int tid  = threadIdx.x;
    const int lane = tid & 31;
    const int wid  = tid >> 5;
    const int wm   = wid >> 2;   // 0..3 : batch-row group (32 rows)
    const int wn   = wid & 3;    // 0..3 : col group
    const int F0   = blockIdx.x * FC;
    const int B0   = blockIdx.y * 128;

    const uint32_t smem_u = smem_to_u32(smf);
    const uint32_t xn_u = smem_u + 16896u * 4u;
    const uint32_t we_u = smem_u + 22016u * 4u;
    const uint32_t wd_u = smem_u + 26368u * 4u;

    // ---- chunk preload: params + seg runs ----
    if (tid == 0) cnt_s[0] = 0;
    for (int i = tid; i < FC; i += 512) {
        int f = F0 + i;
        int s = seg[f];
        segs_s[i] = s;
        benc_s[i] = b_enc[f];
        wdn_s[i]  = g_wdn[f];
        cwf_s[i]  = g_cw[s];
    }
    __syncthreads();
    for (int i = tid; i < FC; i += 512) {
        if (i > 0 && segs_s[i] != segs_s[i - 1]) {
            int j = atomicAdd(cnt_s, 1);
            tmp_s[j] = i;
        }
    }
    __syncthreads();
    if (tid == 0) {
        int c = cnt_s[0];
        for (int a = 1; a < c; a++) {            // tiny insertion sort (c <= 7)
            int v = tmp_s[a]; int b = a - 1;
            while (b >= 0 && tmp_s[b] > v) { tmp_s[b + 1] = tmp_s[b]; b--; }
            tmp_s[b + 1] = v;
        }
        runs_s[0] = 0;
        for (int a = 0; a < c; a++) runs_s[a + 1] = tmp_s[a];
        runs_s[c + 1] = FC;
        for (int r = 0; r <= c; r++) blk_s[r] = segs_s[runs_s[r]];
    }
    __syncthreads();

    float acc2[2][8][4];                          // GEMM2 accum: 32 rows x 64 dm cols / warp
#pragma unroll
    for (int mt = 0; mt < 2; mt++)
#pragma unroll
        for (int nt = 0; nt < 8; nt++)
#pragma unroll
            for (int r = 0; r < 4; r++) acc2[mt][nt][r] = 0.f;

    int cur_r = 0;
    float l1p = 0.f;
    int l0p = 0;

    for (int st = 0; st < NST; st++) {
        const int Fst = F0 + st * 128;

        // ================= GEMM1: out[128b x 128f] = xn @ W_enc =================
        float acc1[2][4][4];
#pragma unroll
        for (int mt = 0; mt < 2; mt++)
#pragma unroll
            for (int nt = 0; nt < 4; nt++)
#pragma unroll
                for (int r = 0; r < 4; r++) acc1[mt][nt][r] = 0.f;

        // stage issue: xn slice [128b x 16k], wenc slice [16k x 128f]
        {
            cpa16(xn_u + 0u + (uint32_t)(tid >> 2) * 80u + (uint32_t)(tid & 3) * 16u,
                  g_xn + (size_t)(B0 + (tid >> 2)) * DM + (tid & 3) * 4);
            cpa16(we_u + 0u + (uint32_t)(tid >> 5) * 544u + (uint32_t)(tid & 31) * 16u,
                  g_wenc32 + (size_t)(tid >> 5) * NF + Fst + (tid & 31) * 4);
            CP_COMMIT();
        }
        for (int s = 0; s < 16; s++) {
            if (s < 15) {
                int b = (s + 1) & 1, k0 = (s + 1) * 16;
                cpa16(xn_u + (uint32_t)b * 10240u + (uint32_t)(tid >> 2) * 80u + (uint32_t)(tid & 3) * 16u,
                      g_xn + (size_t)(B0 + (tid >> 2)) * DM + k0 + (tid & 3) * 4);
                cpa16(we_u + (uint32_t)b * 8704u + (uint32_t)(tid >> 5) * 544u + (uint32_t)(tid & 31) * 16u,
                      g_wenc32 + (size_t)(k0 + (tid >> 5)) * NF + Fst + (tid & 31) * 4);
                CP_COMMIT();
                CP_WAIT1();
            } else {
                CP_WAIT0();
            }
            __syncthreads();
            const float* xb = xn_s + (s & 1) * 2560;
            const float* wb = we_s + (s & 1) * 2176;
#pragma unroll
            for (int kb = 0; kb < 16; kb += 8) {
                uint32_t a[2][4], b[4][2];
#pragma unroll
                for (int mt = 0; mt < 2; mt++) {
                    const float* p = xb + (wm * 32 + mt * 16 + (lane >> 2)) * 20 + kb + (lane & 3);
                    a[mt][0] = __float_as_uint(p[0]);
                    a[mt][1] = __float_as_uint(p[160]);
                    a[mt][2] = __float_as_uint(p[4]);
                    a[mt][3] = __float_as_uint(p[164]);
                }
#pragma unroll
                for (int nt = 0; nt < 4; nt++) {
                    const float* p = wb + (kb + (lane & 3)) * 136 + wn * 32 + nt * 8 + (lane >> 2);
                    b[nt][0] = __float_as_uint(p[0]);
                    b[nt][1] = __float_as_uint(p[544]);
                }
#pragma unroll
                for (int mt = 0; mt < 2; mt++)
#pragma unroll
                    for (int nt = 0; nt < 4; nt++)
                        mma_tf32(acc1[mt][nt], a[mt], b[nt]);
            }
            __syncthreads();
        }

        // ---- epilogue: relu + L1/L0 + stash tf32 acts to smem ----
#pragma unroll
        for (int mt = 0; mt < 2; mt++)
#pragma unroll
            for (int nt = 0; nt < 4; nt++)
#pragma unroll
                for (int r = 0; r < 4; r++) {
                    int row = wm * 32 + mt * 16 + (lane >> 2) + ((r >> 1) << 3);
                    int fl  = wn * 32 + nt * 8 + ((lane & 3) << 1) + (r & 1);
                    int fc  = st * 128 + fl;
                    float act = fmaxf(acc1[mt][nt][r] + benc_s[fc], 0.f);
                    if (act > 0.f) {
                        l0p++;
                        l1p += cwf_s[fc] * __logf(fmaf(10.f * wdn_s[fc], act, 1.f));
                    }
                    acts_s[row * 132 + fl] = __uint_as_float(rna_tf32(act));
                }
        __syncthreads();

        // ================= GEMM2: acc2 += acts @ W_dec (K = 128 features) =================
        {
#pragma unroll
            for (int j = 0; j < 2; j++)
                cpa16(wd_u + 0u + (uint32_t)(tid >> 5) * 1056u + (uint32_t)(tid & 31) * 16u + (uint32_t)j * 512u,
                      g_wdec32 + (size_t)(Fst + (tid >> 5)) * DM + (tid & 31) * 4 + j * 128);
            CP_COMMIT();
        }
        for (int s2 = 0; s2 < 8; s2++) {
            if (s2 < 7) {
                int b = (s2 + 1) & 1, fb = Fst + (s2 + 1) * 16;
#pragma unroll
                for (int j = 0; j < 2; j++)
                    cpa16(wd_u + (uint32_t)b * 16896u + (uint32_t)(tid >> 5) * 1056u + (uint32_t)(tid & 31) * 16u + (uint32_t)j * 512u,
                          g_wdec32 + (size_t)(fb + (tid >> 5)) * DM + (tid & 31) * 4 + j * 128);
                CP_COMMIT();
                CP_WAIT1();
            } else {
                CP_WAIT0();
            }
            __syncthreads();
            const float* wdb = wd_s + (s2 & 1) * 4224;
#pragma unroll
            for (int kb = 0; kb < 16; kb += 8) {
                const int kl  = s2 * 16 + kb;        // subtile-local k
                const int w0  = st * 128 + kl;       // chunk-relative window start
                const int wend = w0 + 8;
                int pcur = w0;
                while (pcur < wend) {
                    int rb = runs_s[cur_r + 1];
                    int q  = (rb < wend) ? rb : wend;
                    bool full = (pcur == w0) && (q == wend);
                    uint32_t a[2][4];
#pragma unroll
                    for (int mt = 0; mt < 2; mt++) {
                        const float* p = acts_s + (wm * 32 + mt * 16 + (lane >> 2)) * 132 + kl + (lane & 3);
                        a[mt][0] = __float_as_uint(p[0]);
                        a[mt][1] = __float_as_uint(p[1056]);
                        a[mt][2] = __float_as_uint(p[4]);
                        a[mt][3] = __float_as_uint(p[1060]);
                    }
                    if (!full) {
                        int f0c = w0 + (lane & 3);
                        bool v0 = (f0c >= pcur) && (f0c < q);
                        bool v1 = (f0c + 4 >= pcur) && (f0c + 4 < q);
#pragma unroll
                        for (int mt = 0; mt < 2; mt++) {
                            if (!v0) { a[mt][0] = 0u; a[mt][1] = 0u; }
                            if (!v1) { a[mt][2] = 0u; a[mt][3] = 0u; }
                        }
                    }
#pragma unroll
                    for (int nt = 0; nt < 8; nt++) {
                        uint32_t b[2];
                        const float* p = wdb + (kb + (lane & 3)) * 264 + wn * 64 + nt * 8 + (lane >> 2);
                        b[0] = __float_as_uint(p[0]);
                        b[1] = __float_as_uint(p[1056]);
#pragma unroll
                        for (int mt = 0; mt < 2; mt++)
                            mma_tf32(acc2[mt][nt], a[mt], b);
                    }
                    if (q == rb) {   // run complete -> flush accumulators
                        float* base = g_blockacc + ((size_t)blk_s[cur_r] * BATCH + B0) * DM;
#pragma unroll
                        for (int mt = 0; mt < 2; mt++)
#pragma unroll
                            for (int nt = 0; nt < 8; nt++)
#pragma unroll
                                for (int r = 0; r < 4; r++) {
                                    int row = wm * 32 + mt * 16 + (lane >> 2) + ((r >> 1) << 3);
                                    int col = wn * 64 + nt * 8 + ((lane & 3) << 1) + (r & 1);
                                    atomicAdd(base + (size_t)row * DM + col, acc2[mt][nt][r]);
                                    acc2[mt][nt][r] = 0.f;
                                }
                        cur_r++;
                    }
                    pcur = q;
                }
            }
            __syncthreads();
        }
    }

    // ---- L1/L0 reduction ----
#pragma unroll
    for (int o = 16; o > 0; o >>= 1) {
        l1p += __shfl_down_sync(0xffffffffu, l1p, o);
        l0p += __shfl_down_sync(0xffffffffu, l0p, o);
    }
    if (lane == 0) {
        atomicAdd(&g_l1, (double)l1p);
        atomicAdd(&g_l0, (unsigned long long)l0p);
    }
}

// ---------------- per-row cumulative-block MSE ----------------
__global__ void k_mse(const float* __restrict__ x, const float* __restrict__ b_dec,
                      const float* __restrict__ bw) {
    __shared__ float sbw[NB];
    __shared__ float red[8];
    int b = blockIdx.x, d = threadIdx.x;
    if (d < NB) sbw[d] = bw[d];
    __syncthreads();
    float xn = x[(size_t)b * DM + d] * g_scale;
    float cum = b_dec[d];
    float t = 0.f;
#pragma unroll
    for (int k = 0; k < NB; k++) {
        cum += g_blockacc[((size_t)k * BATCH + b) * DM + d];
        float diff = cum - xn;
        t += sbw[k] * diff * diff;
    }
#pragma unroll
    for (int o = 16; o > 0; o >>= 1) t += __shfl_down_sync(0xffffffffu, t, o);
    if ((d & 31) == 0) red[d >> 5] = t;
    __syncthreads();
    if (d < 8) {
        t = red[d];
#pragma unroll
        for (int o = 4; o > 0; o >>= 1) t += __shfl_down_sync(0xffu, t, o);
        if (d == 0) atomicAdd(&g_mse, (double)t);
    }
}

__global__ void k_final(const float* __restrict__ l1_scale, float* __restrict__ out) {
    double mse = g_mse / ((double)NB * (double)BATCH);
    double l1  = g_l1 / (double)BATCH;
    float avg_l0 = (float)((double)g_l0 / (double)BATCH);
    float reg = l1_scale[0] * (avg_l0 < 100.0f ? (1.0f - 3e-4f) : (1.0f + 3e-4f));
    out[0] = (float)(mse + (double)reg * (double)l1);
}

// ---------------- launch ----------------
extern "C" void kernel_launch(void* const* d_in, const int* in_sizes, int n_in,
                              void* d_out, int out_size) {
    const float* x     = (const float*)d_in[0];
    const float* W_enc = (const float*)d_in[1];
    const float* b_enc = (const float*)d_in[2];
    const float* W_dec = (const float*)d_in[3];
    const float* b_dec = (const float*)d_in[4];
    const float* bw    = (const float*)d_in[5];
    const float* ravg  = (const float*)d_in[6];
    const float* l1s   = (const float*)d_in[7];
    const int*   seg   = (const int*)d_in[8];
    float* out = (float*)d_out;

    cudaFuncSetAttribute(k_main, cudaFuncAttributeMaxDynamicSharedMemorySize, SMEM_BYTES);

    k_zero<<<2048, 256>>>();
    k_xnorm<<<BATCH / 8, 256>>>(x);
    k_wdn<<<NF / 8, 256>>>(W_dec);
    k_cvt_enc<<<(DM * NF / 4) / 512, 512>>>(W_enc);
    k_cvt_dec<<<(NF * DM / 4) / 512, 512>>>(W_dec);
    k_prep<<<1, 1>>>(ravg, bw);
    k_xn<<<(BATCH * DM / 4) / 512, 512>>>(x);
    dim3 grid(NCH, BATCH / 128);
    k_main<<<grid, 512, SMEM_BYTES>>>(b_enc, seg);
    k_mse<<<BATCH, 256>>>(x, b_dec, bw);
    k_final<<<1, 1>>>(l1s, out);
}